// round 15
// baseline (speedup 1.0000x reference)
#include <cuda_runtime.h>
#include <cuda_bf16.h>
#include <math.h>
#include <stdint.h>

// ---------------- problem constants ----------------
#define NN      65536
#define CH      256
#define GG      64
#define NPG     1024
#define KEIG    32
#define NB      64
#define BD      4
#define NBP     384
#define LAYERS  2
#define EDGES   524288

#define WTOT    491520
#define OFF_ENC   0
#define OFF_SELF0 65536
#define OFF_SELF1 131072
#define OFF_NB0   196608
#define OFF_NB1   262144
#define OFF_DEC   327680
#define OFF_LIN   425984

// ---------------- scratch (device globals; no mallocs allowed) -------------
__device__ float g_h  [NN * CH];
__device__ float g_tmp[NN * CH];
__device__ float g_agg[NN * CH];
__device__ float g_rep[NN * NBP];
__device__ float g_hs [GG * KEIG * CH];
__device__ float g_hs2[GG * KEIG * CH];
__device__ float g_zeros[NBP];
__device__ __nv_bfloat16 g_whi[WTOT];
__device__ __nv_bfloat16 g_wlo[WTOT];
__device__ int g_rowptr[NN + 1];
__device__ int g_cursor[NN];
__device__ int g_csr[EDGES];

__device__ __forceinline__ float gelu_exact(float x) {
    return 0.5f * x * (1.0f + erff(x * 0.7071067811865476f));
}
__device__ __forceinline__ uint32_t pack_bf2(float a, float b) {
    __nv_bfloat162 t = __floats2bfloat162_rn(a, b);
    return *(uint32_t*)&t;
}
__device__ __forceinline__ uint32_t smem_u32(const void* p) {
    uint32_t a;
    asm("{ .reg .u64 t; cvta.to.shared.u64 t, %1; cvt.u32.u64 %0, t; }" : "=r"(a) : "l"(p));
    return a;
}
__device__ __forceinline__ void ldsm_x4(uint32_t* r, uint32_t addr) {
    asm volatile("ldmatrix.sync.aligned.m8n8.x4.shared.b16 {%0,%1,%2,%3}, [%4];"
                 : "=r"(r[0]), "=r"(r[1]), "=r"(r[2]), "=r"(r[3]) : "r"(addr));
}
__device__ __forceinline__ void mma_bf16(float* c, const uint32_t* a, uint32_t b0, uint32_t b1) {
    asm volatile("mma.sync.aligned.m16n8k16.row.col.f32.bf16.bf16.f32 "
                 "{%0,%1,%2,%3}, {%4,%5,%6,%7}, {%8,%9}, {%0,%1,%2,%3};"
                 : "+f"(c[0]), "+f"(c[1]), "+f"(c[2]), "+f"(c[3])
                 : "r"(a[0]), "r"(a[1]), "r"(a[2]), "r"(a[3]), "r"(b0), "r"(b1));
}

// ---------------- fused weight convert+transpose ----------------
__global__ void convert_all(const float* __restrict__ enc, const float* __restrict__ selfw,
                            const float* __restrict__ nbw, const float* __restrict__ dec,
                            const float* __restrict__ lin,
                            __nv_bfloat16* __restrict__ dhi,
                            __nv_bfloat16* __restrict__ dlo) {
    int t = blockIdx.x * blockDim.x + threadIdx.x;
    if (t >= WTOT) return;
    const float* src;
    int local, Ncols, dstoff;
    if (t < OFF_SELF0)      { src = enc;            local = t;              Ncols = 256; dstoff = OFF_ENC; }
    else if (t < OFF_SELF1) { src = selfw;          local = t - OFF_SELF0;  Ncols = 256; dstoff = OFF_SELF0; }
    else if (t < OFF_NB0)   { src = selfw + 65536;  local = t - OFF_SELF1;  Ncols = 256; dstoff = OFF_SELF1; }
    else if (t < OFF_NB1)   { src = nbw;            local = t - OFF_NB0;    Ncols = 256; dstoff = OFF_NB0; }
    else if (t < OFF_DEC)   { src = nbw + 65536;    local = t - OFF_NB1;    Ncols = 256; dstoff = OFF_NB1; }
    else if (t < OFF_LIN)   { src = dec;            local = t - OFF_DEC;    Ncols = 384; dstoff = OFF_DEC; }
    else                    { src = lin;            local = t - OFF_LIN;    Ncols = 256; dstoff = OFF_LIN; }
    int k = local / Ncols, n = local % Ncols;
    float v = src[local];
    __nv_bfloat16 h = __float2bfloat16_rn(v);
    dhi[dstoff + (size_t)n * 256 + k] = h;
    dlo[dstoff + (size_t)n * 256 + k] = __float2bfloat16_rn(v - __bfloat162float(h));
}

// ---------------- CSR build ----------------
__global__ void csr_hist(const int* __restrict__ ei, int* __restrict__ rowptr, int E) {
    int e = blockIdx.x * blockDim.x + threadIdx.x;
    if (e < E) atomicAdd(&rowptr[ei[E + e] + 1], 1);
}
__global__ void csr_scan(int* __restrict__ rowptr, int* __restrict__ cursor) {
    __shared__ int ssum[1024];
    int t = threadIdx.x;
    int base = 1 + t * 64;
    int s = 0;
#pragma unroll 4
    for (int i = 0; i < 64; i++) { s += rowptr[base + i]; rowptr[base + i] = s; }
    ssum[t] = s;
    __syncthreads();
    for (int off = 1; off < 1024; off <<= 1) {
        int v = (t >= off) ? ssum[t - off] : 0;
        __syncthreads();
        ssum[t] += v;
        __syncthreads();
    }
    int excl = (t == 0) ? 0 : ssum[t - 1];
#pragma unroll 4
    for (int i = 0; i < 64; i++) {
        int j = base + i;
        int v = rowptr[j] + excl;
        rowptr[j] = v;
        if (j < NN) cursor[j] = v;
    }
    if (t == 0) cursor[0] = 0;
}
__global__ void csr_fill(const int* __restrict__ ei, int* __restrict__ cursor,
                         int* __restrict__ csr, int E) {
    int e = blockIdx.x * blockDim.x + threadIdx.x;
    if (e < E) {
        int pos = atomicAdd(&cursor[ei[E + e]], 1);
        csr[pos] = ei[e];
    }
}

// ---------------- gather: 2 warps per node, MLP-4 per warp ----------------
__global__ __launch_bounds__(256)
void agg_gather(const float* __restrict__ h, const int* __restrict__ rowptr,
                const int* __restrict__ csr, float* __restrict__ agg) {
    const int gw   = (blockIdx.x * 256 + threadIdx.x) >> 5;
    const int node = gw >> 1;
    const int slab = gw & 1;
    const int lane = threadIdx.x & 31;
    if (node >= NN) return;
    const int start = __ldg(&rowptr[node]);
    const int end   = __ldg(&rowptr[node + 1]);
    const float4* hv = (const float4*)h;
    const int col = slab * 32 + lane;
    float4 a0 = make_float4(0.f, 0.f, 0.f, 0.f);
    float4 a1 = make_float4(0.f, 0.f, 0.f, 0.f);
    float4 a2 = make_float4(0.f, 0.f, 0.f, 0.f);
    float4 a3 = make_float4(0.f, 0.f, 0.f, 0.f);
    int e = start;
    for (; e + 4 <= end; e += 4) {
        int s[4];
#pragma unroll
        for (int j = 0; j < 4; j++) s[j] = __ldg(&csr[e + j]);
        float4 v0 = __ldg(hv + (size_t)s[0] * 64 + col);
        float4 v1 = __ldg(hv + (size_t)s[1] * 64 + col);
        float4 v2 = __ldg(hv + (size_t)s[2] * 64 + col);
        float4 v3 = __ldg(hv + (size_t)s[3] * 64 + col);
        a0.x += v0.x; a0.y += v0.y; a0.z += v0.z; a0.w += v0.w;
        a1.x += v1.x; a1.y += v1.y; a1.z += v1.z; a1.w += v1.w;
        a2.x += v2.x; a2.y += v2.y; a2.z += v2.z; a2.w += v2.w;
        a3.x += v3.x; a3.y += v3.y; a3.z += v3.z; a3.w += v3.w;
    }
    for (; e < end; e++) {
        int s0 = __ldg(&csr[e]);
        float4 v0 = __ldg(hv + (size_t)s0 * 64 + col);
        a0.x += v0.x; a0.y += v0.y; a0.z += v0.z; a0.w += v0.w;
    }
    float4 r;
    r.x = (a0.x + a1.x) + (a2.x + a3.x);
    r.y = (a0.y + a1.y) + (a2.y + a3.y);
    r.z = (a0.z + a1.z) + (a2.z + a3.z);
    r.w = (a0.w + a1.w) + (a2.w + a3.w);
    ((float4*)agg)[(size_t)node * 64 + col] = r;
}

// ---------------- HMMA GEMM (R13-proven): CTA 128x64, 256 thr, 2 CTAs/SM ---
#define PITCH 40
#define SM_AHI 0
#define SM_ALO 10240
#define SM_BHI 20480
#define SM_BLO 25600
#define SM_BUF 30720
#define SM_TOT 61440

template <int EPI>
__global__ void __launch_bounds__(256, 2)
tgemm(const float* __restrict__ A,
      const __nv_bfloat16* __restrict__ Whi, const __nv_bfloat16* __restrict__ Wlo,
      const float* __restrict__ bias,
      const float* __restrict__ extra, const float* __restrict__ resid,
      float* __restrict__ C, int Nn) {
    extern __shared__ __align__(16) char smem[];

    const int tid  = threadIdx.x;
    const int lane = tid & 31;
    const int wid  = tid >> 5;
    const int warpM = wid & 3;
    const int warpN = wid >> 2;
    const int rowBase = blockIdx.y * 128;
    const int colBase = blockIdx.x * 64;

    const float* Ab = A + (size_t)rowBase * 256;
    const __nv_bfloat16* Wh = Whi + (size_t)colBase * 256;
    const __nv_bfloat16* Wl = Wlo + (size_t)colBase * 256;

    const uint32_t aFragOff = (uint32_t)(warpM * 32 + (lane & 15)) * (PITCH * 2)
                              + (lane >> 4) * 16;
    const int g = lane >> 3, lr = lane & 7;
    const uint32_t bFragOff = (uint32_t)(warpN * 32 + ((g >> 1) << 3) + lr) * (PITCH * 2)
                              + (g & 1) * 16;
    const uint32_t smemBase = smem_u32(smem);

    float c[2][4][4];
#pragma unroll
    for (int mi = 0; mi < 2; mi++)
#pragma unroll
        for (int ni = 0; ni < 4; ni++)
#pragma unroll
            for (int e = 0; e < 4; e++) c[mi][ni][e] = 0.f;

    const int aR = tid >> 3;
    const int aKg = tid & 7;
    const int bR = tid >> 2;
    const int bKg = tid & 3;

    float4 pa[4];
    uint4  pbh, pbl;

    auto prefetch = [&](int kn) {
        const float* Ap = Ab + kn * 32;
        const __nv_bfloat16* Whp = Wh + kn * 32;
        const __nv_bfloat16* Wlp = Wl + kn * 32;
#pragma unroll
        for (int i = 0; i < 4; i++)
            pa[i] = *(const float4*)&Ap[(size_t)(aR + i * 32) * 256 + aKg * 4];
        pbh = *(const uint4*)(Whp + (size_t)bR * 256 + bKg * 8);
        pbl = *(const uint4*)(Wlp + (size_t)bR * 256 + bKg * 8);
    };
    auto stage = [&](int buf) {
        char* base = smem + buf * SM_BUF;
#pragma unroll
        for (int i = 0; i < 4; i++) {
            int r = aR + i * 32;
            float4 v = pa[i];
            __nv_bfloat162 h01 = __floats2bfloat162_rn(v.x, v.y);
            __nv_bfloat162 h23 = __floats2bfloat162_rn(v.z, v.w);
            float l0 = v.x - __bfloat162float(h01.x);
            float l1 = v.y - __bfloat162float(h01.y);
            float l2 = v.z - __bfloat162float(h23.x);
            float l3 = v.w - __bfloat162float(h23.y);
            *(uint2*)(base + SM_AHI + r * (PITCH * 2) + aKg * 8) =
                make_uint2(*(uint32_t*)&h01, *(uint32_t*)&h23);
            *(uint2*)(base + SM_ALO + r * (PITCH * 2) + aKg * 8) =
                make_uint2(pack_bf2(l0, l1), pack_bf2(l2, l3));
        }
        *(uint4*)(base + SM_BHI + bR * (PITCH * 2) + bKg * 16) = pbh;
        *(uint4*)(base + SM_BLO + bR * (PITCH * 2) + bKg * 16) = pbl;
    };

    prefetch(0);
    stage(0);
    __syncthreads();
    prefetch(1);

    for (int kc = 0; kc < 8; kc++) {
        if (kc + 1 < 8) stage((kc + 1) & 1);
        if (kc + 2 < 8) prefetch(kc + 2);

        const uint32_t bufOff = smemBase + (kc & 1) * SM_BUF;
        const uint32_t aHiB = bufOff + SM_AHI + aFragOff;
        const uint32_t aLoB = bufOff + SM_ALO + aFragOff;
        const uint32_t bHiB = bufOff + SM_BHI + bFragOff;
        const uint32_t bLoB = bufOff + SM_BLO + bFragOff;

#pragma unroll
        for (int ks = 0; ks < 2; ks++) {
            const uint32_t kso = ks * 32;
            uint32_t ah[2][4], al[2][4];
#pragma unroll
            for (int mi = 0; mi < 2; mi++) {
                ldsm_x4(ah[mi], aHiB + kso + mi * 16 * (PITCH * 2));
                ldsm_x4(al[mi], aLoB + kso + mi * 16 * (PITCH * 2));
            }
            uint32_t bh[2][4], bl[2][4];
#pragma unroll
            for (int n2 = 0; n2 < 2; n2++) {
                ldsm_x4(bh[n2], bHiB + kso + n2 * 16 * (PITCH * 2));
                ldsm_x4(bl[n2], bLoB + kso + n2 * 16 * (PITCH * 2));
            }
#pragma unroll
            for (int mi = 0; mi < 2; mi++)
#pragma unroll
                for (int ni = 0; ni < 4; ni++) {
                    int n2 = ni >> 1, j = (ni & 1) * 2;
                    mma_bf16(c[mi][ni], ah[mi], bh[n2][j], bh[n2][j + 1]);
                    mma_bf16(c[mi][ni], ah[mi], bl[n2][j], bl[n2][j + 1]);
                    mma_bf16(c[mi][ni], al[mi], bh[n2][j], bh[n2][j + 1]);
                }
        }
        __syncthreads();
    }

#pragma unroll
    for (int mi = 0; mi < 2; mi++) {
        int row0 = rowBase + warpM * 32 + mi * 16 + (lane >> 2);
#pragma unroll
        for (int ni = 0; ni < 4; ni++) {
            int col = colBase + warpN * 32 + ni * 8 + (lane & 3) * 2;
            float b0 = bias[col], b1 = bias[col + 1];
#pragma unroll
            for (int half = 0; half < 2; half++) {
                int row = row0 + half * 8;
                float v0 = c[mi][ni][half * 2 + 0] + b0;
                float v1 = c[mi][ni][half * 2 + 1] + b1;
                if (EPI == 3) {
                    float2 ex = *(const float2*)&extra[(size_t)row * Nn + col];
                    v0 += ex.x; v1 += ex.y;
                }
                if (EPI >= 1) { v0 = gelu_exact(v0); v1 = gelu_exact(v1); }
                if (EPI == 3) {
                    float2 rs = *(const float2*)&resid[(size_t)row * Nn + col];
                    v0 += rs.x; v1 += rs.y;
                }
                *(float2*)&C[(size_t)row * Nn + col] = make_float2(v0, v1);
            }
        }
    }
}

// ---------------- Householder ----------------
__device__ __forceinline__ void build_Q(float p0, float p1, float p2, float p3,
                                        float p4, float p5, float Q[4][4]) {
#pragma unroll
    for (int i = 0; i < 4; i++)
#pragma unroll
        for (int j = 0; j < 4; j++) Q[i][j] = (i == j) ? 1.f : 0.f;
    {
        float inv = 2.f / (1.f + p0 * p0 + p1 * p1 + p2 * p2);
#pragma unroll
        for (int i = 0; i < 4; i++) {
            float qv = Q[i][0] + Q[i][1] * p0 + Q[i][2] * p1 + Q[i][3] * p2;
            float s = inv * qv;
            Q[i][0] -= s; Q[i][1] -= s * p0; Q[i][2] -= s * p1; Q[i][3] -= s * p2;
        }
    }
    {
        float inv = 2.f / (1.f + p3 * p3 + p4 * p4);
#pragma unroll
        for (int i = 0; i < 4; i++) {
            float qv = Q[i][1] + Q[i][2] * p3 + Q[i][3] * p4;
            float s = inv * qv;
            Q[i][1] -= s; Q[i][2] -= s * p3; Q[i][3] -= s * p4;
        }
    }
    {
        float inv = 2.f / (1.f + p5 * p5);
#pragma unroll
        for (int i = 0; i < 4; i++) {
            float qv = Q[i][2] + Q[i][3] * p5;
            float s = inv * qv;
            Q[i][2] -= s; Q[i][3] -= s * p5;
        }
    }
}

__global__ void hh_kernel(const float* __restrict__ rep, const float* __restrict__ x,
                          float* __restrict__ hv) {
    int t = blockIdx.x * blockDim.x + threadIdx.x;
    if (t >= NN * NB) return;
    int n = t >> 6;
    int b = t & 63;
    const float* p = rep + (size_t)n * NBP + b * 6;
    float Q[4][4];
    build_Q(p[0], p[1], p[2], p[3], p[4], p[5], Q);
    float4 xv = *(const float4*)&x[(size_t)n * CH + b * 4];
    float xr[4] = {xv.x, xv.y, xv.z, xv.w};
    float4 ov; float* o = &ov.x;
#pragma unroll
    for (int cc = 0; cc < 4; cc++)
        o[cc] = Q[cc][0] * xr[0] + Q[cc][1] * xr[1] + Q[cc][2] * xr[2] + Q[cc][3] * xr[3];
    *(float4*)&hv[(size_t)n * CH + b * 4] = ov;
}

// spec_fwd split over node chunks: partial ev^T @ hv into hs (pre-zeroed)
__global__ void spec_fwd(const float* __restrict__ ev, const float* __restrict__ hv,
                         float* __restrict__ hs) {
    const int g = blockIdx.x;
    const int cc = blockIdx.y * 128 + threadIdx.x;
    const int nbase = g * NPG + blockIdx.z * 128;
    __shared__ float evs[8][KEIG];
    float acc[KEIG];
#pragma unroll
    for (int k = 0; k < KEIG; k++) acc[k] = 0.f;
    for (int n0 = 0; n0 < 128; n0 += 8) {
        __syncthreads();
        for (int i = threadIdx.x; i < 8 * KEIG; i += 128) {
            int r = i >> 5, kk = i & 31;
            evs[r][kk] = ev[(size_t)(nbase + n0 + r) * KEIG + kk];
        }
        __syncthreads();
#pragma unroll
        for (int r = 0; r < 8; r++) {
            float hval = hv[(size_t)(nbase + n0 + r) * CH + cc];
#pragma unroll
            for (int k = 0; k < KEIG; k++) acc[k] += evs[r][k] * hval;
        }
    }
#pragma unroll
    for (int k = 0; k < KEIG; k++) {
        float* dst = &hs[(size_t)(g * KEIG + k) * CH + cc];
        asm volatile("red.global.add.f32 [%0], %1;" :: "l"(dst), "f"(acc[k]) : "memory");
    }
}

__global__ void scale_hs(float* __restrict__ hs, const float* __restrict__ eigval,
                         const float* __restrict__ taus) {
    int t = blockIdx.x * blockDim.x + threadIdx.x;
    int cc = t & (CH - 1);
    int gk = t >> 8;
    float f = expf(-eigval[gk] * taus[cc >> 2]);
    hs[t] *= f;
}

// fused spec_bwd + Q^T apply: out[node,ch] = sum_d Q[d][ch%4] * hl[node, 4*(ch/4)+d]
// where hl = ev @ hs2 + lin_b, computed per thread then exchanged via shfl(width=4).
__global__ void spec_bwd_final(const float* __restrict__ ev, const float* __restrict__ hs2,
                               const float* __restrict__ bias, const float* __restrict__ rep,
                               float* __restrict__ out) {
    const int g = blockIdx.x;
    const int nbase = g * NPG + blockIdx.y * 64;
    __shared__ float hss[KEIG][CH];
    __shared__ float evs[64][KEIG];
    for (int i = 0; i < KEIG; i++)
        hss[i][threadIdx.x] = hs2[(size_t)(g * KEIG + i) * CH + threadIdx.x];
    for (int i = threadIdx.x; i < 64 * KEIG; i += 256) {
        int r = i >> 5, kk = i & 31;
        evs[r][kk] = ev[(size_t)(nbase + r) * KEIG + kk];
    }
    __syncthreads();
    const float b = bias[threadIdx.x];
    const int bundle = threadIdx.x >> 2;
    const int comp = threadIdx.x & 3;
    for (int r = 0; r < 64; r++) {
        const int node = nbase + r;
        float s = b;
#pragma unroll
        for (int k = 0; k < KEIG; k++) s += evs[r][k] * hss[k][threadIdx.x];
        const float* p = rep + (size_t)node * NBP + bundle * 6;
        float Q[4][4];
        build_Q(__ldg(p), __ldg(p + 1), __ldg(p + 2),
                __ldg(p + 3), __ldg(p + 4), __ldg(p + 5), Q);
        float o = 0.f;
#pragma unroll
        for (int d = 0; d < 4; d++) {
            float hld = __shfl_sync(0xffffffffu, s, d, 4);
            o += Q[d][comp] * hld;
        }
        out[(size_t)node * CH + threadIdx.x] = o;
    }
}

// ---------------- orchestration (forked-stream capture) ----------------
extern "C" void kernel_launch(void* const* d_in, const int* in_sizes, int n_in,
                              void* d_out, int out_size) {
    const float* x      = (const float*)d_in[0];
    const float* eigvec = (const float*)d_in[1];
    const float* eigval = (const float*)d_in[2];
    const float* taus   = (const float*)d_in[3];
    const float* enc_w  = (const float*)d_in[4];
    const float* enc_b  = (const float*)d_in[5];
    const float* self_w = (const float*)d_in[6];
    const float* self_b = (const float*)d_in[7];
    const float* nb_w   = (const float*)d_in[8];
    const float* nb_b   = (const float*)d_in[9];
    const float* dec_w  = (const float*)d_in[10];
    const float* dec_b  = (const float*)d_in[11];
    const float* lin_w  = (const float*)d_in[12];
    const float* lin_b  = (const float*)d_in[13];
    const int*   ei     = (const int*)d_in[14];
    float* out = (float*)d_out;

    const int E = in_sizes[14] / 2;

    float *h, *tmp, *agg, *rep, *hs, *hs2, *zeros;
    __nv_bfloat16 *whi, *wlo;
    int *rowptr, *cursor, *csr;
    cudaGetSymbolAddress((void**)&h,      g_h);
    cudaGetSymbolAddress((void**)&tmp,    g_tmp);
    cudaGetSymbolAddress((void**)&agg,    g_agg);
    cudaGetSymbolAddress((void**)&rep,    g_rep);
    cudaGetSymbolAddress((void**)&hs,     g_hs);
    cudaGetSymbolAddress((void**)&hs2,    g_hs2);
    cudaGetSymbolAddress((void**)&zeros,  g_zeros);
    cudaGetSymbolAddress((void**)&whi,    g_whi);
    cudaGetSymbolAddress((void**)&wlo,    g_wlo);
    cudaGetSymbolAddress((void**)&rowptr, g_rowptr);
    cudaGetSymbolAddress((void**)&cursor, g_cursor);
    cudaGetSymbolAddress((void**)&csr,    g_csr);

    cudaFuncSetAttribute(tgemm<0>, cudaFuncAttributeMaxDynamicSharedMemorySize, SM_TOT);
    cudaFuncSetAttribute(tgemm<1>, cudaFuncAttributeMaxDynamicSharedMemorySize, SM_TOT);
    cudaFuncSetAttribute(tgemm<3>, cudaFuncAttributeMaxDynamicSharedMemorySize, SM_TOT);

    // side stream + events: created per call, intentionally not destroyed
    cudaStream_t s2;
    cudaStreamCreateWithFlags(&s2, cudaStreamNonBlocking);
    cudaEvent_t evRoot, evH, evG0, evT, evG1;
    cudaEventCreateWithFlags(&evRoot, cudaEventDisableTiming);
    cudaEventCreateWithFlags(&evH,    cudaEventDisableTiming);
    cudaEventCreateWithFlags(&evG0,   cudaEventDisableTiming);
    cudaEventCreateWithFlags(&evT,    cudaEventDisableTiming);
    cudaEventCreateWithFlags(&evG1,   cudaEventDisableTiming);

    dim3 gemm_grid(CH / 64, NN / 128);        // (4, 512)
    dim3 dec_grid(NBP / 64, NN / 128);        // (6, 512)
    dim3 hs_grid(CH / 64, (GG * KEIG) / 128); // (4, 16)

    // main: weight convert, zero small buffers; fork side stream for CSR build
    convert_all<<<(WTOT + 255) / 256, 256>>>(enc_w, self_w, nb_w, dec_w, lin_w, whi, wlo);
    cudaMemsetAsync(zeros, 0, NBP * sizeof(float));
    cudaMemsetAsync(hs, 0, (size_t)GG * KEIG * CH * sizeof(float));
    cudaEventRecord(evRoot, 0);
    cudaStreamWaitEvent(s2, evRoot, 0);
    cudaMemsetAsync(rowptr, 0, (NN + 1) * sizeof(int), s2);
    csr_hist<<<(E + 255) / 256, 256, 0, s2>>>(ei, rowptr, E);
    csr_scan<<<1, 1024, 0, s2>>>(rowptr, cursor);
    csr_fill<<<(E + 255) / 256, 256, 0, s2>>>(ei, cursor, csr, E);

    // main: h = gelu(x @ enc_w + enc_b)
    tgemm<1><<<gemm_grid, 256, SM_TOT>>>(x, whi + OFF_ENC, wlo + OFF_ENC, enc_b,
                                         nullptr, nullptr, h, CH);
    cudaEventRecord(evH, 0);

    // ---- layer 0: gather(h) on s2 || self-GEMM(h) on main ----
    cudaStreamWaitEvent(s2, evH, 0);
    agg_gather<<<NN / 4, 256, 0, s2>>>(h, rowptr, csr, agg);
    cudaEventRecord(evG0, s2);

    tgemm<0><<<gemm_grid, 256, SM_TOT>>>(h, whi + OFF_SELF0, wlo + OFF_SELF0, self_b,
                                         nullptr, nullptr, rep, CH);
    cudaStreamWaitEvent(0, evG0, 0);
    tgemm<3><<<gemm_grid, 256, SM_TOT>>>(agg, whi + OFF_NB0, wlo + OFF_NB0, nb_b,
                                         rep, h, tmp, CH);
    cudaEventRecord(evT, 0);

    // ---- layer 1: gather(tmp) on s2 || self-GEMM(tmp) on main ----
    cudaStreamWaitEvent(s2, evT, 0);
    agg_gather<<<NN / 4, 256, 0, s2>>>(tmp, rowptr, csr, agg);
    cudaEventRecord(evG1, s2);

    tgemm<0><<<gemm_grid, 256, SM_TOT>>>(tmp, whi + OFF_SELF1, wlo + OFF_SELF1, self_b + CH,
                                         nullptr, nullptr, rep, CH);
    cudaStreamWaitEvent(0, evG1, 0);
    tgemm<3><<<gemm_grid, 256, SM_TOT>>>(agg, whi + OFF_NB1, wlo + OFF_NB1, nb_b + CH,
                                         rep, tmp, h, CH);

    // node_rep = h @ dec_w + dec_b
    tgemm<0><<<dec_grid, 256, SM_TOT>>>(h, whi + OFF_DEC, wlo + OFF_DEC, dec_b,
                                        nullptr, nullptr, rep, NBP);

    // Householder Q + forward rotate (hv into tmp)
    hh_kernel<<<NN * NB / 256, 256>>>(rep, x, tmp);

    // spectral filter: partial reductions into hs, scale, tiny GEMM, fused bwd+final
    spec_fwd<<<dim3(GG, 2, 8), 128>>>(eigvec, tmp, hs);
    scale_hs<<<(GG * KEIG * CH) / 256, 256>>>(hs, eigval, taus);
    tgemm<0><<<hs_grid, 256, SM_TOT>>>(hs, whi + OFF_LIN, wlo + OFF_LIN, zeros,
                                       nullptr, nullptr, hs2, CH);
    spec_bwd_final<<<dim3(GG, NPG / 64), 256>>>(eigvec, hs2, lin_b, rep, out);
}

// round 16
// speedup vs baseline: 1.0902x; 1.0902x over previous
#include <cuda_runtime.h>
#include <cuda_bf16.h>
#include <math.h>
#include <stdint.h>

// ---------------- problem constants ----------------
#define NN      65536
#define CH      256
#define GG      64
#define NPG     1024
#define KEIG    32
#define NB      64
#define BD      4
#define NBP     384
#define LAYERS  2
#define EDGES   524288

#define WTOT    491520
#define OFF_ENC   0
#define OFF_SELF0 65536
#define OFF_SELF1 131072
#define OFF_NB0   196608
#define OFF_NB1   262144
#define OFF_DEC   327680
#define OFF_LIN   425984

// ---------------- scratch (device globals; no mallocs allowed) -------------
__device__ float g_h  [NN * CH];
__device__ float g_tmp[NN * CH];
__device__ float g_agg[NN * CH];
__device__ float g_rep[NN * NBP];
__device__ float g_hs [GG * KEIG * CH];
__device__ float g_hs2[GG * KEIG * CH];
__device__ __nv_bfloat16 g_whi[WTOT];
__device__ __nv_bfloat16 g_wlo[WTOT];
__device__ int g_rowptr[NN + 1];
__device__ int g_cursor[NN];
__device__ int g_csr[EDGES];

__device__ __forceinline__ float gelu_exact(float x) {
    return 0.5f * x * (1.0f + erff(x * 0.7071067811865476f));
}
__device__ __forceinline__ uint32_t pack_bf2(float a, float b) {
    __nv_bfloat162 t = __floats2bfloat162_rn(a, b);
    return *(uint32_t*)&t;
}
__device__ __forceinline__ uint32_t smem_u32(const void* p) {
    uint32_t a;
    asm("{ .reg .u64 t; cvta.to.shared.u64 t, %1; cvt.u32.u64 %0, t; }" : "=r"(a) : "l"(p));
    return a;
}
__device__ __forceinline__ void ldsm_x4(uint32_t* r, uint32_t addr) {
    asm volatile("ldmatrix.sync.aligned.m8n8.x4.shared.b16 {%0,%1,%2,%3}, [%4];"
                 : "=r"(r[0]), "=r"(r[1]), "=r"(r[2]), "=r"(r[3]) : "r"(addr));
}
__device__ __forceinline__ void mma_bf16(float* c, const uint32_t* a, uint32_t b0, uint32_t b1) {
    asm volatile("mma.sync.aligned.m16n8k16.row.col.f32.bf16.bf16.f32 "
                 "{%0,%1,%2,%3}, {%4,%5,%6,%7}, {%8,%9}, {%0,%1,%2,%3};"
                 : "+f"(c[0]), "+f"(c[1]), "+f"(c[2]), "+f"(c[3])
                 : "r"(a[0]), "r"(a[1]), "r"(a[2]), "r"(a[3]), "r"(b0), "r"(b1));
}

// ---------------- fused weight convert+transpose ----------------
__global__ void convert_all(const float* __restrict__ enc, const float* __restrict__ selfw,
                            const float* __restrict__ nbw, const float* __restrict__ dec,
                            const float* __restrict__ lin,
                            __nv_bfloat16* __restrict__ dhi,
                            __nv_bfloat16* __restrict__ dlo) {
    int t = blockIdx.x * blockDim.x + threadIdx.x;
    if (t >= WTOT) return;
    const float* src;
    int local, Ncols, dstoff;
    if (t < OFF_SELF0)      { src = enc;            local = t;              Ncols = 256; dstoff = OFF_ENC; }
    else if (t < OFF_SELF1) { src = selfw;          local = t - OFF_SELF0;  Ncols = 256; dstoff = OFF_SELF0; }
    else if (t < OFF_NB0)   { src = selfw + 65536;  local = t - OFF_SELF1;  Ncols = 256; dstoff = OFF_SELF1; }
    else if (t < OFF_NB1)   { src = nbw;            local = t - OFF_NB0;    Ncols = 256; dstoff = OFF_NB0; }
    else if (t < OFF_DEC)   { src = nbw + 65536;    local = t - OFF_NB1;    Ncols = 256; dstoff = OFF_NB1; }
    else if (t < OFF_LIN)   { src = dec;            local = t - OFF_DEC;    Ncols = 384; dstoff = OFF_DEC; }
    else                    { src = lin;            local = t - OFF_LIN;    Ncols = 256; dstoff = OFF_LIN; }
    int k = local / Ncols, n = local % Ncols;
    float v = src[local];
    __nv_bfloat16 h = __float2bfloat16_rn(v);
    dhi[dstoff + (size_t)n * 256 + k] = h;
    dlo[dstoff + (size_t)n * 256 + k] = __float2bfloat16_rn(v - __bfloat162float(h));
}

// ---------------- CSR build ----------------
__global__ void csr_hist(const int* __restrict__ ei, int* __restrict__ rowptr, int E) {
    int e = blockIdx.x * blockDim.x + threadIdx.x;
    if (e < E) atomicAdd(&rowptr[ei[E + e] + 1], 1);
}
__global__ void csr_scan(int* __restrict__ rowptr, int* __restrict__ cursor) {
    __shared__ int ssum[1024];
    int t = threadIdx.x;
    int base = 1 + t * 64;
    int s = 0;
#pragma unroll 4
    for (int i = 0; i < 64; i++) { s += rowptr[base + i]; rowptr[base + i] = s; }
    ssum[t] = s;
    __syncthreads();
    for (int off = 1; off < 1024; off <<= 1) {
        int v = (t >= off) ? ssum[t - off] : 0;
        __syncthreads();
        ssum[t] += v;
        __syncthreads();
    }
    int excl = (t == 0) ? 0 : ssum[t - 1];
#pragma unroll 4
    for (int i = 0; i < 64; i++) {
        int j = base + i;
        int v = rowptr[j] + excl;
        rowptr[j] = v;
        if (j < NN) cursor[j] = v;
    }
    if (t == 0) cursor[0] = 0;
}
__global__ void csr_fill(const int* __restrict__ ei, int* __restrict__ cursor,
                         int* __restrict__ csr, int E) {
    int e = blockIdx.x * blockDim.x + threadIdx.x;
    if (e < E) {
        int pos = atomicAdd(&cursor[ei[E + e]], 1);
        csr[pos] = ei[e];
    }
}

// ---------------- gather: 2 warps per node, MLP-4 per warp ----------------
__global__ __launch_bounds__(256)
void agg_gather(const float* __restrict__ h, const int* __restrict__ rowptr,
                const int* __restrict__ csr, float* __restrict__ agg) {
    const int gw   = (blockIdx.x * 256 + threadIdx.x) >> 5;
    const int node = gw >> 1;
    const int slab = gw & 1;
    const int lane = threadIdx.x & 31;
    if (node >= NN) return;
    const int start = __ldg(&rowptr[node]);
    const int end   = __ldg(&rowptr[node + 1]);
    const float4* hv = (const float4*)h;
    const int col = slab * 32 + lane;
    float4 a0 = make_float4(0.f, 0.f, 0.f, 0.f);
    float4 a1 = make_float4(0.f, 0.f, 0.f, 0.f);
    float4 a2 = make_float4(0.f, 0.f, 0.f, 0.f);
    float4 a3 = make_float4(0.f, 0.f, 0.f, 0.f);
    int e = start;
    for (; e + 4 <= end; e += 4) {
        int s[4];
#pragma unroll
        for (int j = 0; j < 4; j++) s[j] = __ldg(&csr[e + j]);
        float4 v0 = __ldg(hv + (size_t)s[0] * 64 + col);
        float4 v1 = __ldg(hv + (size_t)s[1] * 64 + col);
        float4 v2 = __ldg(hv + (size_t)s[2] * 64 + col);
        float4 v3 = __ldg(hv + (size_t)s[3] * 64 + col);
        a0.x += v0.x; a0.y += v0.y; a0.z += v0.z; a0.w += v0.w;
        a1.x += v1.x; a1.y += v1.y; a1.z += v1.z; a1.w += v1.w;
        a2.x += v2.x; a2.y += v2.y; a2.z += v2.z; a2.w += v2.w;
        a3.x += v3.x; a3.y += v3.y; a3.z += v3.z; a3.w += v3.w;
    }
    for (; e < end; e++) {
        int s0 = __ldg(&csr[e]);
        float4 v0 = __ldg(hv + (size_t)s0 * 64 + col);
        a0.x += v0.x; a0.y += v0.y; a0.z += v0.z; a0.w += v0.w;
    }
    float4 r;
    r.x = (a0.x + a1.x) + (a2.x + a3.x);
    r.y = (a0.y + a1.y) + (a2.y + a3.y);
    r.z = (a0.z + a1.z) + (a2.z + a3.z);
    r.w = (a0.w + a1.w) + (a2.w + a3.w);
    ((float4*)agg)[(size_t)node * 64 + col] = r;
}

// ---------------- HMMA GEMM (R13-proven): CTA 128x64, 256 thr, 2 CTAs/SM ---
// EPI 0: acc+bias ; EPI 1: gelu(acc+bias) ; EPI 2: plain acc (no bias)
// EPI 3: gelu(acc+bias+extra)+resid
#define PITCH 40
#define SM_AHI 0
#define SM_ALO 10240
#define SM_BHI 20480
#define SM_BLO 25600
#define SM_BUF 30720
#define SM_TOT 61440

template <int EPI>
__global__ void __launch_bounds__(256, 2)
tgemm(const float* __restrict__ A,
      const __nv_bfloat16* __restrict__ Whi, const __nv_bfloat16* __restrict__ Wlo,
      const float* __restrict__ bias,
      const float* __restrict__ extra, const float* __restrict__ resid,
      float* __restrict__ C, int Nn) {
    extern __shared__ __align__(16) char smem[];

    const int tid  = threadIdx.x;
    const int lane = tid & 31;
    const int wid  = tid >> 5;
    const int warpM = wid & 3;
    const int warpN = wid >> 2;
    const int rowBase = blockIdx.y * 128;
    const int colBase = blockIdx.x * 64;

    const float* Ab = A + (size_t)rowBase * 256;
    const __nv_bfloat16* Wh = Whi + (size_t)colBase * 256;
    const __nv_bfloat16* Wl = Wlo + (size_t)colBase * 256;

    const uint32_t aFragOff = (uint32_t)(warpM * 32 + (lane & 15)) * (PITCH * 2)
                              + (lane >> 4) * 16;
    const int g = lane >> 3, lr = lane & 7;
    const uint32_t bFragOff = (uint32_t)(warpN * 32 + ((g >> 1) << 3) + lr) * (PITCH * 2)
                              + (g & 1) * 16;
    const uint32_t smemBase = smem_u32(smem);

    float c[2][4][4];
#pragma unroll
    for (int mi = 0; mi < 2; mi++)
#pragma unroll
        for (int ni = 0; ni < 4; ni++)
#pragma unroll
            for (int e = 0; e < 4; e++) c[mi][ni][e] = 0.f;

    const int aR = tid >> 3;
    const int aKg = tid & 7;
    const int bR = tid >> 2;
    const int bKg = tid & 3;

    float4 pa[4];
    uint4  pbh, pbl;

    auto prefetch = [&](int kn) {
        const float* Ap = Ab + kn * 32;
        const __nv_bfloat16* Whp = Wh + kn * 32;
        const __nv_bfloat16* Wlp = Wl + kn * 32;
#pragma unroll
        for (int i = 0; i < 4; i++)
            pa[i] = *(const float4*)&Ap[(size_t)(aR + i * 32) * 256 + aKg * 4];
        pbh = *(const uint4*)(Whp + (size_t)bR * 256 + bKg * 8);
        pbl = *(const uint4*)(Wlp + (size_t)bR * 256 + bKg * 8);
    };
    auto stage = [&](int buf) {
        char* base = smem + buf * SM_BUF;
#pragma unroll
        for (int i = 0; i < 4; i++) {
            int r = aR + i * 32;
            float4 v = pa[i];
            __nv_bfloat162 h01 = __floats2bfloat162_rn(v.x, v.y);
            __nv_bfloat162 h23 = __floats2bfloat162_rn(v.z, v.w);
            float l0 = v.x - __bfloat162float(h01.x);
            float l1 = v.y - __bfloat162float(h01.y);
            float l2 = v.z - __bfloat162float(h23.x);
            float l3 = v.w - __bfloat162float(h23.y);
            *(uint2*)(base + SM_AHI + r * (PITCH * 2) + aKg * 8) =
                make_uint2(*(uint32_t*)&h01, *(uint32_t*)&h23);
            *(uint2*)(base + SM_ALO + r * (PITCH * 2) + aKg * 8) =
                make_uint2(pack_bf2(l0, l1), pack_bf2(l2, l3));
        }
        *(uint4*)(base + SM_BHI + bR * (PITCH * 2) + bKg * 16) = pbh;
        *(uint4*)(base + SM_BLO + bR * (PITCH * 2) + bKg * 16) = pbl;
    };

    prefetch(0);
    stage(0);
    __syncthreads();
    prefetch(1);

    for (int kc = 0; kc < 8; kc++) {
        if (kc + 1 < 8) stage((kc + 1) & 1);
        if (kc + 2 < 8) prefetch(kc + 2);

        const uint32_t bufOff = smemBase + (kc & 1) * SM_BUF;
        const uint32_t aHiB = bufOff + SM_AHI + aFragOff;
        const uint32_t aLoB = bufOff + SM_ALO + aFragOff;
        const uint32_t bHiB = bufOff + SM_BHI + bFragOff;
        const uint32_t bLoB = bufOff + SM_BLO + bFragOff;

#pragma unroll
        for (int ks = 0; ks < 2; ks++) {
            const uint32_t kso = ks * 32;
            uint32_t ah[2][4], al[2][4];
#pragma unroll
            for (int mi = 0; mi < 2; mi++) {
                ldsm_x4(ah[mi], aHiB + kso + mi * 16 * (PITCH * 2));
                ldsm_x4(al[mi], aLoB + kso + mi * 16 * (PITCH * 2));
            }
            uint32_t bh[2][4], bl[2][4];
#pragma unroll
            for (int n2 = 0; n2 < 2; n2++) {
                ldsm_x4(bh[n2], bHiB + kso + n2 * 16 * (PITCH * 2));
                ldsm_x4(bl[n2], bLoB + kso + n2 * 16 * (PITCH * 2));
            }
#pragma unroll
            for (int mi = 0; mi < 2; mi++)
#pragma unroll
                for (int ni = 0; ni < 4; ni++) {
                    int n2 = ni >> 1, j = (ni & 1) * 2;
                    mma_bf16(c[mi][ni], ah[mi], bh[n2][j], bh[n2][j + 1]);
                    mma_bf16(c[mi][ni], ah[mi], bl[n2][j], bl[n2][j + 1]);
                    mma_bf16(c[mi][ni], al[mi], bh[n2][j], bh[n2][j + 1]);
                }
        }
        __syncthreads();
    }

#pragma unroll
    for (int mi = 0; mi < 2; mi++) {
        int row0 = rowBase + warpM * 32 + mi * 16 + (lane >> 2);
#pragma unroll
        for (int ni = 0; ni < 4; ni++) {
            int col = colBase + warpN * 32 + ni * 8 + (lane & 3) * 2;
            float b0 = 0.f, b1 = 0.f;
            if (EPI != 2) { b0 = bias[col]; b1 = bias[col + 1]; }
#pragma unroll
            for (int half = 0; half < 2; half++) {
                int row = row0 + half * 8;
                float v0 = c[mi][ni][half * 2 + 0] + b0;
                float v1 = c[mi][ni][half * 2 + 1] + b1;
                if (EPI == 3) {
                    float2 ex = *(const float2*)&extra[(size_t)row * Nn + col];
                    v0 += ex.x; v1 += ex.y;
                }
                if (EPI == 1 || EPI == 3) { v0 = gelu_exact(v0); v1 = gelu_exact(v1); }
                if (EPI == 3) {
                    float2 rs = *(const float2*)&resid[(size_t)row * Nn + col];
                    v0 += rs.x; v1 += rs.y;
                }
                *(float2*)&C[(size_t)row * Nn + col] = make_float2(v0, v1);
            }
        }
    }
}

// ---------------- Householder ----------------
__device__ __forceinline__ void build_Q(float p0, float p1, float p2, float p3,
                                        float p4, float p5, float Q[4][4]) {
#pragma unroll
    for (int i = 0; i < 4; i++)
#pragma unroll
        for (int j = 0; j < 4; j++) Q[i][j] = (i == j) ? 1.f : 0.f;
    {
        float inv = 2.f / (1.f + p0 * p0 + p1 * p1 + p2 * p2);
#pragma unroll
        for (int i = 0; i < 4; i++) {
            float qv = Q[i][0] + Q[i][1] * p0 + Q[i][2] * p1 + Q[i][3] * p2;
            float s = inv * qv;
            Q[i][0] -= s; Q[i][1] -= s * p0; Q[i][2] -= s * p1; Q[i][3] -= s * p2;
        }
    }
    {
        float inv = 2.f / (1.f + p3 * p3 + p4 * p4);
#pragma unroll
        for (int i = 0; i < 4; i++) {
            float qv = Q[i][1] + Q[i][2] * p3 + Q[i][3] * p4;
            float s = inv * qv;
            Q[i][1] -= s; Q[i][2] -= s * p3; Q[i][3] -= s * p4;
        }
    }
    {
        float inv = 2.f / (1.f + p5 * p5);
#pragma unroll
        for (int i = 0; i < 4; i++) {
            float qv = Q[i][2] + Q[i][3] * p5;
            float s = inv * qv;
            Q[i][2] -= s; Q[i][3] -= s * p5;
        }
    }
}

__global__ void hh_kernel(const float* __restrict__ rep, const float* __restrict__ x,
                          float* __restrict__ hv) {
    int t = blockIdx.x * blockDim.x + threadIdx.x;
    if (t >= NN * NB) return;
    int n = t >> 6;
    int b = t & 63;
    const float* p = rep + (size_t)n * NBP + b * 6;
    float Q[4][4];
    build_Q(p[0], p[1], p[2], p[3], p[4], p[5], Q);
    float4 xv = *(const float4*)&x[(size_t)n * CH + b * 4];
    float xr[4] = {xv.x, xv.y, xv.z, xv.w};
    float4 ov; float* o = &ov.x;
#pragma unroll
    for (int cc = 0; cc < 4; cc++)
        o[cc] = Q[cc][0] * xr[0] + Q[cc][1] * xr[1] + Q[cc][2] * xr[2] + Q[cc][3] * xr[3];
    *(float4*)&hv[(size_t)n * CH + b * 4] = ov;
}

// spec_fwd: partial ev^T @ hv, scaled by exp(-eigval*tau) (linear in partials),
// reduced into pre-zeroed hs via red.global.add
__global__ void spec_fwd(const float* __restrict__ ev, const float* __restrict__ hv,
                         const float* __restrict__ eigval, const float* __restrict__ taus,
                         float* __restrict__ hs) {
    const int g = blockIdx.x;
    const int cc = blockIdx.y * 128 + threadIdx.x;
    const int nbase = g * NPG + blockIdx.z * 128;
    __shared__ float evs[8][KEIG];
    float acc[KEIG];
#pragma unroll
    for (int k = 0; k < KEIG; k++) acc[k] = 0.f;
    for (int n0 = 0; n0 < 128; n0 += 8) {
        __syncthreads();
        for (int i = threadIdx.x; i < 8 * KEIG; i += 128) {
            int r = i >> 5, kk = i & 31;
            evs[r][kk] = ev[(size_t)(nbase + n0 + r) * KEIG + kk];
        }
        __syncthreads();
#pragma unroll
        for (int r = 0; r < 8; r++) {
            float hval = hv[(size_t)(nbase + n0 + r) * CH + cc];
#pragma unroll
            for (int k = 0; k < KEIG; k++) acc[k] += evs[r][k] * hval;
        }
    }
    const float tau = taus[cc >> 2];
#pragma unroll
    for (int k = 0; k < KEIG; k++) {
        float f = expf(-eigval[g * KEIG + k] * tau);
        float* dst = &hs[(size_t)(g * KEIG + k) * CH + cc];
        float val = acc[k] * f;
        asm volatile("red.global.add.f32 [%0], %1;" :: "l"(dst), "f"(val) : "memory");
    }
}

// spec_bwd with fused lin bias: out = ev @ hs2 + bias
__global__ void spec_bwd(const float* __restrict__ ev, const float* __restrict__ hs2,
                         const float* __restrict__ bias, float* __restrict__ out) {
    const int g = blockIdx.x;
    const int nbase = g * NPG + blockIdx.y * 64;
    __shared__ float hss[KEIG][CH];
    __shared__ float evs[64][KEIG];
    for (int i = 0; i < KEIG; i++)
        hss[i][threadIdx.x] = hs2[(size_t)(g * KEIG + i) * CH + threadIdx.x];
    for (int i = threadIdx.x; i < 64 * KEIG; i += 256) {
        int r = i >> 5, kk = i & 31;
        evs[r][kk] = ev[(size_t)(nbase + r) * KEIG + kk];
    }
    __syncthreads();
    float b = bias[threadIdx.x];
    for (int r = 0; r < 64; r++) {
        float s = b;
#pragma unroll
        for (int k = 0; k < KEIG; k++) s += evs[r][k] * hss[k][threadIdx.x];
        out[(size_t)(nbase + r) * CH + threadIdx.x] = s;
    }
}

__global__ void final_kernel(const float* __restrict__ rep,
                             const float* __restrict__ hl,
                             float* __restrict__ out) {
    int t = blockIdx.x * blockDim.x + threadIdx.x;
    if (t >= NN * NB) return;
    int n = t >> 6;
    int b = t & 63;
    const float* p = rep + (size_t)n * NBP + b * 6;
    float Q[4][4];
    build_Q(p[0], p[1], p[2], p[3], p[4], p[5], Q);
    float4 hvv = *(const float4*)&hl[(size_t)n * CH + b * 4];
    float hr[4] = {hvv.x, hvv.y, hvv.z, hvv.w};
    float4 ov; float* o = &ov.x;
#pragma unroll
    for (int cc = 0; cc < 4; cc++)
        o[cc] = Q[0][cc] * hr[0] + Q[1][cc] * hr[1] + Q[2][cc] * hr[2] + Q[3][cc] * hr[3];
    *(float4*)&out[(size_t)n * CH + b * 4] = ov;
}

// ---------------- orchestration (forked-stream capture) ----------------
extern "C" void kernel_launch(void* const* d_in, const int* in_sizes, int n_in,
                              void* d_out, int out_size) {
    const float* x      = (const float*)d_in[0];
    const float* eigvec = (const float*)d_in[1];
    const float* eigval = (const float*)d_in[2];
    const float* taus   = (const float*)d_in[3];
    const float* enc_w  = (const float*)d_in[4];
    const float* enc_b  = (const float*)d_in[5];
    const float* self_w = (const float*)d_in[6];
    const float* self_b = (const float*)d_in[7];
    const float* nb_w   = (const float*)d_in[8];
    const float* nb_b   = (const float*)d_in[9];
    const float* dec_w  = (const float*)d_in[10];
    const float* dec_b  = (const float*)d_in[11];
    const float* lin_w  = (const float*)d_in[12];
    const float* lin_b  = (const float*)d_in[13];
    const int*   ei     = (const int*)d_in[14];
    float* out = (float*)d_out;

    const int E = in_sizes[14] / 2;

    float *h, *tmp, *agg, *rep, *hs, *hs2;
    __nv_bfloat16 *whi, *wlo;
    int *rowptr, *cursor, *csr;
    cudaGetSymbolAddress((void**)&h,      g_h);
    cudaGetSymbolAddress((void**)&tmp,    g_tmp);
    cudaGetSymbolAddress((void**)&agg,    g_agg);
    cudaGetSymbolAddress((void**)&rep,    g_rep);
    cudaGetSymbolAddress((void**)&hs,     g_hs);
    cudaGetSymbolAddress((void**)&hs2,    g_hs2);
    cudaGetSymbolAddress((void**)&whi,    g_whi);
    cudaGetSymbolAddress((void**)&wlo,    g_wlo);
    cudaGetSymbolAddress((void**)&rowptr, g_rowptr);
    cudaGetSymbolAddress((void**)&cursor, g_cursor);
    cudaGetSymbolAddress((void**)&csr,    g_csr);

    cudaFuncSetAttribute(tgemm<0>, cudaFuncAttributeMaxDynamicSharedMemorySize, SM_TOT);
    cudaFuncSetAttribute(tgemm<1>, cudaFuncAttributeMaxDynamicSharedMemorySize, SM_TOT);
    cudaFuncSetAttribute(tgemm<2>, cudaFuncAttributeMaxDynamicSharedMemorySize, SM_TOT);
    cudaFuncSetAttribute(tgemm<3>, cudaFuncAttributeMaxDynamicSharedMemorySize, SM_TOT);

    // side stream + events: created per call, intentionally not destroyed
    cudaStream_t s2;
    cudaStreamCreateWithFlags(&s2, cudaStreamNonBlocking);
    cudaEvent_t evRoot, evH, evG0, evT, evG1;
    cudaEventCreateWithFlags(&evRoot, cudaEventDisableTiming);
    cudaEventCreateWithFlags(&evH,    cudaEventDisableTiming);
    cudaEventCreateWithFlags(&evG0,   cudaEventDisableTiming);
    cudaEventCreateWithFlags(&evT,    cudaEventDisableTiming);
    cudaEventCreateWithFlags(&evG1,   cudaEventDisableTiming);

    dim3 gemm_grid(CH / 64, NN / 128);        // (4, 512)
    dim3 dec_grid(NBP / 64, NN / 128);        // (6, 512)
    dim3 hs_grid(CH / 64, (GG * KEIG) / 128); // (4, 16)

    // main: weight convert, zero hs; fork side stream for CSR build
    convert_all<<<(WTOT + 255) / 256, 256>>>(enc_w, self_w, nb_w, dec_w, lin_w, whi, wlo);
    cudaMemsetAsync(hs, 0, (size_t)GG * KEIG * CH * sizeof(float));
    cudaEventRecord(evRoot, 0);
    cudaStreamWaitEvent(s2, evRoot, 0);
    cudaMemsetAsync(rowptr, 0, (NN + 1) * sizeof(int), s2);
    csr_hist<<<(E + 255) / 256, 256, 0, s2>>>(ei, rowptr, E);
    csr_scan<<<1, 1024, 0, s2>>>(rowptr, cursor);
    csr_fill<<<(E + 255) / 256, 256, 0, s2>>>(ei, cursor, csr, E);

    // main: h = gelu(x @ enc_w + enc_b)
    tgemm<1><<<gemm_grid, 256, SM_TOT>>>(x, whi + OFF_ENC, wlo + OFF_ENC, enc_b,
                                         nullptr, nullptr, h, CH);
    cudaEventRecord(evH, 0);

    // ---- layer 0: gather(h) on s2 || self-GEMM(h) on main ----
    cudaStreamWaitEvent(s2, evH, 0);
    agg_gather<<<NN / 4, 256, 0, s2>>>(h, rowptr, csr, agg);
    cudaEventRecord(evG0, s2);

    tgemm<0><<<gemm_grid, 256, SM_TOT>>>(h, whi + OFF_SELF0, wlo + OFF_SELF0, self_b,
                                         nullptr, nullptr, rep, CH);
    cudaStreamWaitEvent(0, evG0, 0);
    tgemm<3><<<gemm_grid, 256, SM_TOT>>>(agg, whi + OFF_NB0, wlo + OFF_NB0, nb_b,
                                         rep, h, tmp, CH);
    cudaEventRecord(evT, 0);

    // ---- layer 1: gather(tmp) on s2 || self-GEMM(tmp) on main ----
    cudaStreamWaitEvent(s2, evT, 0);
    agg_gather<<<NN / 4, 256, 0, s2>>>(tmp, rowptr, csr, agg);
    cudaEventRecord(evG1, s2);

    tgemm<0><<<gemm_grid, 256, SM_TOT>>>(tmp, whi + OFF_SELF1, wlo + OFF_SELF1, self_b + CH,
                                         nullptr, nullptr, rep, CH);
    cudaStreamWaitEvent(0, evG1, 0);
    tgemm<3><<<gemm_grid, 256, SM_TOT>>>(agg, whi + OFF_NB1, wlo + OFF_NB1, nb_b + CH,
                                         rep, tmp, h, CH);

    // node_rep = h @ dec_w + dec_b
    tgemm<0><<<dec_grid, 256, SM_TOT>>>(h, whi + OFF_DEC, wlo + OFF_DEC, dec_b,
                                        nullptr, nullptr, rep, NBP);

    // Householder Q + forward rotate (hv into tmp)
    hh_kernel<<<NN * NB / 256, 256>>>(rep, x, tmp);

    // spectral filter: scaled partial reductions into hs, tiny GEMM, bwd, final
    spec_fwd<<<dim3(GG, 2, 8), 128>>>(eigvec, tmp, eigval, taus, hs);
    tgemm<2><<<hs_grid, 256, SM_TOT>>>(hs, whi + OFF_LIN, wlo + OFF_LIN, nullptr,
                                       nullptr, nullptr, hs2, CH);
    spec_bwd<<<dim3(GG, NPG / 64), 256>>>(eigvec, hs2, lin_b, tmp);

    // out = Q^T @ hl
    final_kernel<<<NN * NB / 256, 256>>>(rep, tmp, out);
}

// round 17
// speedup vs baseline: 1.1106x; 1.0187x over previous
#include <cuda_runtime.h>
#include <cuda_bf16.h>
#include <math.h>
#include <stdint.h>

// ---------------- problem constants ----------------
#define NN      65536
#define CH      256
#define GG      64
#define NPG     1024
#define KEIG    32
#define NB      64
#define BD      4
#define NBP     384
#define LAYERS  2
#define EDGES   524288

#define WTOT    491520
#define OFF_ENC   0
#define OFF_SELF0 65536
#define OFF_SELF1 131072
#define OFF_NB0   196608
#define OFF_NB1   262144
#define OFF_DEC   327680
#define OFF_LIN   425984

// ---------------- scratch (device globals; no mallocs allowed) -------------
__device__ float g_h  [NN * CH];
__device__ float g_tmp[NN * CH];
__device__ float g_agg[NN * CH];
__device__ float g_rep[NN * NBP];
__device__ float g_hs [GG * KEIG * CH];
__device__ float g_hs2[GG * KEIG * CH];
__device__ __nv_bfloat16 g_whi[WTOT];
__device__ __nv_bfloat16 g_wlo[WTOT];
__device__ int g_rowptr[NN + 1];
__device__ int g_cursor[NN];
__device__ int g_csr[EDGES];

__device__ __forceinline__ float gelu_exact(float x) {
    return 0.5f * x * (1.0f + erff(x * 0.7071067811865476f));
}
__device__ __forceinline__ uint32_t pack_bf2(float a, float b) {
    __nv_bfloat162 t = __floats2bfloat162_rn(a, b);
    return *(uint32_t*)&t;
}
__device__ __forceinline__ uint32_t smem_u32(const void* p) {
    uint32_t a;
    asm("{ .reg .u64 t; cvta.to.shared.u64 t, %1; cvt.u32.u64 %0, t; }" : "=r"(a) : "l"(p));
    return a;
}
__device__ __forceinline__ void ldsm_x4(uint32_t* r, uint32_t addr) {
    asm volatile("ldmatrix.sync.aligned.m8n8.x4.shared.b16 {%0,%1,%2,%3}, [%4];"
                 : "=r"(r[0]), "=r"(r[1]), "=r"(r[2]), "=r"(r[3]) : "r"(addr));
}
__device__ __forceinline__ void mma_bf16(float* c, const uint32_t* a, uint32_t b0, uint32_t b1) {
    asm volatile("mma.sync.aligned.m16n8k16.row.col.f32.bf16.bf16.f32 "
                 "{%0,%1,%2,%3}, {%4,%5,%6,%7}, {%8,%9}, {%0,%1,%2,%3};"
                 : "+f"(c[0]), "+f"(c[1]), "+f"(c[2]), "+f"(c[3])
                 : "r"(a[0]), "r"(a[1]), "r"(a[2]), "r"(a[3]), "r"(b0), "r"(b1));
}
__device__ __forceinline__ void cp16(uint32_t dst, const void* src) {
    asm volatile("cp.async.cg.shared.global [%0], [%1], 16;" :: "r"(dst), "l"(src));
}
__device__ __forceinline__ void cp_commit() {
    asm volatile("cp.async.commit_group;" ::: "memory");
}
__device__ __forceinline__ void cp_wait0() {
    asm volatile("cp.async.wait_group 0;" ::: "memory");
}

// ---------------- fused weight convert+transpose ----------------
__global__ void convert_all(const float* __restrict__ enc, const float* __restrict__ selfw,
                            const float* __restrict__ nbw, const float* __restrict__ dec,
                            const float* __restrict__ lin,
                            __nv_bfloat16* __restrict__ dhi,
                            __nv_bfloat16* __restrict__ dlo) {
    int t = blockIdx.x * blockDim.x + threadIdx.x;
    if (t >= WTOT) return;
    const float* src;
    int local, Ncols, dstoff;
    if (t < OFF_SELF0)      { src = enc;            local = t;              Ncols = 256; dstoff = OFF_ENC; }
    else if (t < OFF_SELF1) { src = selfw;          local = t - OFF_SELF0;  Ncols = 256; dstoff = OFF_SELF0; }
    else if (t < OFF_NB0)   { src = selfw + 65536;  local = t - OFF_SELF1;  Ncols = 256; dstoff = OFF_SELF1; }
    else if (t < OFF_NB1)   { src = nbw;            local = t - OFF_NB0;    Ncols = 256; dstoff = OFF_NB0; }
    else if (t < OFF_DEC)   { src = nbw + 65536;    local = t - OFF_NB1;    Ncols = 256; dstoff = OFF_NB1; }
    else if (t < OFF_LIN)   { src = dec;            local = t - OFF_DEC;    Ncols = 384; dstoff = OFF_DEC; }
    else                    { src = lin;            local = t - OFF_LIN;    Ncols = 256; dstoff = OFF_LIN; }
    int k = local / Ncols, n = local % Ncols;
    float v = src[local];
    __nv_bfloat16 h = __float2bfloat16_rn(v);
    dhi[dstoff + (size_t)n * 256 + k] = h;
    dlo[dstoff + (size_t)n * 256 + k] = __float2bfloat16_rn(v - __bfloat162float(h));
}

// ---------------- CSR build ----------------
__global__ void csr_hist(const int* __restrict__ ei, int* __restrict__ rowptr, int E) {
    int e = blockIdx.x * blockDim.x + threadIdx.x;
    if (e < E) atomicAdd(&rowptr[ei[E + e] + 1], 1);
}
__global__ void csr_scan(int* __restrict__ rowptr, int* __restrict__ cursor) {
    __shared__ int ssum[1024];
    int t = threadIdx.x;
    int base = 1 + t * 64;
    int s = 0;
#pragma unroll 4
    for (int i = 0; i < 64; i++) { s += rowptr[base + i]; rowptr[base + i] = s; }
    ssum[t] = s;
    __syncthreads();
    for (int off = 1; off < 1024; off <<= 1) {
        int v = (t >= off) ? ssum[t - off] : 0;
        __syncthreads();
        ssum[t] += v;
        __syncthreads();
    }
    int excl = (t == 0) ? 0 : ssum[t - 1];
#pragma unroll 4
    for (int i = 0; i < 64; i++) {
        int j = base + i;
        int v = rowptr[j] + excl;
        rowptr[j] = v;
        if (j < NN) cursor[j] = v;
    }
    if (t == 0) cursor[0] = 0;
}
__global__ void csr_fill(const int* __restrict__ ei, int* __restrict__ cursor,
                         int* __restrict__ csr, int E) {
    int e = blockIdx.x * blockDim.x + threadIdx.x;
    if (e < E) {
        int pos = atomicAdd(&cursor[ei[E + e]], 1);
        csr[pos] = ei[e];
    }
}

// ---------------- gather: 2 warps per node, MLP-4 per warp ----------------
__global__ __launch_bounds__(256)
void agg_gather(const float* __restrict__ h, const int* __restrict__ rowptr,
                const int* __restrict__ csr, float* __restrict__ agg) {
    const int gw   = (blockIdx.x * 256 + threadIdx.x) >> 5;
    const int node = gw >> 1;
    const int slab = gw & 1;
    const int lane = threadIdx.x & 31;
    if (node >= NN) return;
    const int start = __ldg(&rowptr[node]);
    const int end   = __ldg(&rowptr[node + 1]);
    const float4* hv = (const float4*)h;
    const int col = slab * 32 + lane;
    float4 a0 = make_float4(0.f, 0.f, 0.f, 0.f);
    float4 a1 = make_float4(0.f, 0.f, 0.f, 0.f);
    float4 a2 = make_float4(0.f, 0.f, 0.f, 0.f);
    float4 a3 = make_float4(0.f, 0.f, 0.f, 0.f);
    int e = start;
    for (; e + 4 <= end; e += 4) {
        int s[4];
#pragma unroll
        for (int j = 0; j < 4; j++) s[j] = __ldg(&csr[e + j]);
        float4 v0 = __ldg(hv + (size_t)s[0] * 64 + col);
        float4 v1 = __ldg(hv + (size_t)s[1] * 64 + col);
        float4 v2 = __ldg(hv + (size_t)s[2] * 64 + col);
        float4 v3 = __ldg(hv + (size_t)s[3] * 64 + col);
        a0.x += v0.x; a0.y += v0.y; a0.z += v0.z; a0.w += v0.w;
        a1.x += v1.x; a1.y += v1.y; a1.z += v1.z; a1.w += v1.w;
        a2.x += v2.x; a2.y += v2.y; a2.z += v2.z; a2.w += v2.w;
        a3.x += v3.x; a3.y += v3.y; a3.z += v3.z; a3.w += v3.w;
    }
    for (; e < end; e++) {
        int s0 = __ldg(&csr[e]);
        float4 v0 = __ldg(hv + (size_t)s0 * 64 + col);
        a0.x += v0.x; a0.y += v0.y; a0.z += v0.z; a0.w += v0.w;
    }
    float4 r;
    r.x = (a0.x + a1.x) + (a2.x + a3.x);
    r.y = (a0.y + a1.y) + (a2.y + a3.y);
    r.z = (a0.z + a1.z) + (a2.z + a3.z);
    r.w = (a0.w + a1.w) + (a2.w + a3.w);
    ((float4*)agg)[(size_t)node * 64 + col] = r;
}

// ---------------- HMMA GEMM: CTA 128x64, 256 thr, 2 CTAs/SM ----------------
// A via registers (fp32 -> bf16 hi/lo conversion); B via cp.async (already bf16).
// EPI 0: acc+bias ; EPI 1: gelu(acc+bias) ; EPI 2: plain acc (no bias)
// EPI 3: gelu(acc+bias+extra)+resid
#define PITCH 40
#define SM_AHI 0
#define SM_ALO 10240
#define SM_BHI 20480
#define SM_BLO 25600
#define SM_BUF 30720
#define SM_TOT 61440

template <int EPI>
__global__ void __launch_bounds__(256, 2)
tgemm(const float* __restrict__ A,
      const __nv_bfloat16* __restrict__ Whi, const __nv_bfloat16* __restrict__ Wlo,
      const float* __restrict__ bias,
      const float* __restrict__ extra, const float* __restrict__ resid,
      float* __restrict__ C, int Nn) {
    extern __shared__ __align__(16) char smem[];

    const int tid  = threadIdx.x;
    const int lane = tid & 31;
    const int wid  = tid >> 5;
    const int warpM = wid & 3;
    const int warpN = wid >> 2;
    const int rowBase = blockIdx.y * 128;
    const int colBase = blockIdx.x * 64;

    const float* Ab = A + (size_t)rowBase * 256;
    const __nv_bfloat16* Wh = Whi + (size_t)colBase * 256;
    const __nv_bfloat16* Wl = Wlo + (size_t)colBase * 256;

    const uint32_t aFragOff = (uint32_t)(warpM * 32 + (lane & 15)) * (PITCH * 2)
                              + (lane >> 4) * 16;
    const int g = lane >> 3, lr = lane & 7;
    const uint32_t bFragOff = (uint32_t)(warpN * 32 + ((g >> 1) << 3) + lr) * (PITCH * 2)
                              + (g & 1) * 16;
    const uint32_t smemBase = smem_u32(smem);

    float c[2][4][4];
#pragma unroll
    for (int mi = 0; mi < 2; mi++)
#pragma unroll
        for (int ni = 0; ni < 4; ni++)
#pragma unroll
            for (int e = 0; e < 4; e++) c[mi][ni][e] = 0.f;

    const int aR = tid >> 3;
    const int aKg = tid & 7;
    const int bR = tid >> 2;
    const int bKg = tid & 3;

    const uint32_t bDstOff = (uint32_t)bR * (PITCH * 2) + bKg * 16;

    float4 pa[4];

    auto prefetchA = [&](int kn) {
        const float* Ap = Ab + kn * 32;
#pragma unroll
        for (int i = 0; i < 4; i++)
            pa[i] = *(const float4*)&Ap[(size_t)(aR + i * 32) * 256 + aKg * 4];
    };
    auto stageA = [&](int buf) {
        char* base = smem + buf * SM_BUF;
#pragma unroll
        for (int i = 0; i < 4; i++) {
            int r = aR + i * 32;
            float4 v = pa[i];
            __nv_bfloat162 h01 = __floats2bfloat162_rn(v.x, v.y);
            __nv_bfloat162 h23 = __floats2bfloat162_rn(v.z, v.w);
            float l0 = v.x - __bfloat162float(h01.x);
            float l1 = v.y - __bfloat162float(h01.y);
            float l2 = v.z - __bfloat162float(h23.x);
            float l3 = v.w - __bfloat162float(h23.y);
            *(uint2*)(base + SM_AHI + r * (PITCH * 2) + aKg * 8) =
                make_uint2(*(uint32_t*)&h01, *(uint32_t*)&h23);
            *(uint2*)(base + SM_ALO + r * (PITCH * 2) + aKg * 8) =
                make_uint2(pack_bf2(l0, l1), pack_bf2(l2, l3));
        }
    };
    auto cpB = [&](int kn, int buf) {
        const __nv_bfloat16* Whp = Wh + kn * 32 + (size_t)bR * 256 + bKg * 8;
        const __nv_bfloat16* Wlp = Wl + kn * 32 + (size_t)bR * 256 + bKg * 8;
        uint32_t base = smemBase + buf * SM_BUF;
        cp16(base + SM_BHI + bDstOff, Whp);
        cp16(base + SM_BLO + bDstOff, Wlp);
    };

    // preamble: chunk 0
    prefetchA(0);
    cpB(0, 0);
    cp_commit();
    stageA(0);
    cp_wait0();
    __syncthreads();
    prefetchA(1);

    for (int kc = 0; kc < 8; kc++) {
        if (kc + 1 < 8) {
            stageA((kc + 1) & 1);
            cpB(kc + 1, (kc + 1) & 1);
            cp_commit();
        }
        if (kc + 2 < 8) prefetchA(kc + 2);

        const uint32_t bufOff = smemBase + (kc & 1) * SM_BUF;
        const uint32_t aHiB = bufOff + SM_AHI + aFragOff;
        const uint32_t aLoB = bufOff + SM_ALO + aFragOff;
        const uint32_t bHiB = bufOff + SM_BHI + bFragOff;
        const uint32_t bLoB = bufOff + SM_BLO + bFragOff;

#pragma unroll
        for (int ks = 0; ks < 2; ks++) {
            const uint32_t kso = ks * 32;
            uint32_t ah[2][4], al[2][4];
#pragma unroll
            for (int mi = 0; mi < 2; mi++) {
                ldsm_x4(ah[mi], aHiB + kso + mi * 16 * (PITCH * 2));
                ldsm_x4(al[mi], aLoB + kso + mi * 16 * (PITCH * 2));
            }
            uint32_t bh[2][4], bl[2][4];
#pragma unroll
            for (int n2 = 0; n2 < 2; n2++) {
                ldsm_x4(bh[n2], bHiB + kso + n2 * 16 * (PITCH * 2));
                ldsm_x4(bl[n2], bLoB + kso + n2 * 16 * (PITCH * 2));
            }
#pragma unroll
            for (int mi = 0; mi < 2; mi++)
#pragma unroll
                for (int ni = 0; ni < 4; ni++) {
                    int n2 = ni >> 1, j = (ni & 1) * 2;
                    mma_bf16(c[mi][ni], ah[mi], bh[n2][j], bh[n2][j + 1]);
                    mma_bf16(c[mi][ni], ah[mi], bl[n2][j], bl[n2][j + 1]);
                    mma_bf16(c[mi][ni], al[mi], bh[n2][j], bh[n2][j + 1]);
                }
        }
        if (kc + 1 < 8) cp_wait0();
        __syncthreads();
    }

#pragma unroll
    for (int mi = 0; mi < 2; mi++) {
        int row0 = rowBase + warpM * 32 + mi * 16 + (lane >> 2);
#pragma unroll
        for (int ni = 0; ni < 4; ni++) {
            int col = colBase + warpN * 32 + ni * 8 + (lane & 3) * 2;
            float b0 = 0.f, b1 = 0.f;
            if (EPI != 2) { b0 = bias[col]; b1 = bias[col + 1]; }
#pragma unroll
            for (int half = 0; half < 2; half++) {
                int row = row0 + half * 8;
                float v0 = c[mi][ni][half * 2 + 0] + b0;
                float v1 = c[mi][ni][half * 2 + 1] + b1;
                if (EPI == 3) {
                    float2 ex = *(const float2*)&extra[(size_t)row * Nn + col];
                    v0 += ex.x; v1 += ex.y;
                }
                if (EPI == 1 || EPI == 3) { v0 = gelu_exact(v0); v1 = gelu_exact(v1); }
                if (EPI == 3) {
                    float2 rs = *(const float2*)&resid[(size_t)row * Nn + col];
                    v0 += rs.x; v1 += rs.y;
                }
                *(float2*)&C[(size_t)row * Nn + col] = make_float2(v0, v1);
            }
        }
    }
}

// ---------------- Householder ----------------
__device__ __forceinline__ void build_Q(float p0, float p1, float p2, float p3,
                                        float p4, float p5, float Q[4][4]) {
#pragma unroll
    for (int i = 0; i < 4; i++)
#pragma unroll
        for (int j = 0; j < 4; j++) Q[i][j] = (i == j) ? 1.f : 0.f;
    {
        float inv = 2.f / (1.f + p0 * p0 + p1 * p1 + p2 * p2);
#pragma unroll
        for (int i = 0; i < 4; i++) {
            float qv = Q[i][0] + Q[i][1] * p0 + Q[i][2] * p1 + Q[i][3] * p2;
            float s = inv * qv;
            Q[i][0] -= s; Q[i][1] -= s * p0; Q[i][2] -= s * p1; Q[i][3] -= s * p2;
        }
    }
    {
        float inv = 2.f / (1.f + p3 * p3 + p4 * p4);
#pragma unroll
        for (int i = 0; i < 4; i++) {
            float qv = Q[i][1] + Q[i][2] * p3 + Q[i][3] * p4;
            float s = inv * qv;
            Q[i][1] -= s; Q[i][2] -= s * p3; Q[i][3] -= s * p4;
        }
    }
    {
        float inv = 2.f / (1.f + p5 * p5);
#pragma unroll
        for (int i = 0; i < 4; i++) {
            float qv = Q[i][2] + Q[i][3] * p5;
            float s = inv * qv;
            Q[i][2] -= s; Q[i][3] -= s * p5;
        }
    }
}

__global__ void hh_kernel(const float* __restrict__ rep, const float* __restrict__ x,
                          float* __restrict__ hv) {
    int t = blockIdx.x * blockDim.x + threadIdx.x;
    if (t >= NN * NB) return;
    int n = t >> 6;
    int b = t & 63;
    const float* p = rep + (size_t)n * NBP + b * 6;
    float Q[4][4];
    build_Q(p[0], p[1], p[2], p[3], p[4], p[5], Q);
    float4 xv = *(const float4*)&x[(size_t)n * CH + b * 4];
    float xr[4] = {xv.x, xv.y, xv.z, xv.w};
    float4 ov; float* o = &ov.x;
#pragma unroll
    for (int cc = 0; cc < 4; cc++)
        o[cc] = Q[cc][0] * xr[0] + Q[cc][1] * xr[1] + Q[cc][2] * xr[2] + Q[cc][3] * xr[3];
    *(float4*)&hv[(size_t)n * CH + b * 4] = ov;
}

// spec_fwd: partial ev^T @ hv, scaled by exp(-eigval*tau), red into zeroed hs
__global__ void spec_fwd(const float* __restrict__ ev, const float* __restrict__ hv,
                         const float* __restrict__ eigval, const float* __restrict__ taus,
                         float* __restrict__ hs) {
    const int g = blockIdx.x;
    const int cc = blockIdx.y * 128 + threadIdx.x;
    const int nbase = g * NPG + blockIdx.z * 128;
    __shared__ float evs[8][KEIG];
    float acc[KEIG];
#pragma unroll
    for (int k = 0; k < KEIG; k++) acc[k] = 0.f;
    for (int n0 = 0; n0 < 128; n0 += 8) {
        __syncthreads();
        for (int i = threadIdx.x; i < 8 * KEIG; i += 128) {
            int r = i >> 5, kk = i & 31;
            evs[r][kk] = ev[(size_t)(nbase + n0 + r) * KEIG + kk];
        }
        __syncthreads();
#pragma unroll
        for (int r = 0; r < 8; r++) {
            float hval = hv[(size_t)(nbase + n0 + r) * CH + cc];
#pragma unroll
            for (int k = 0; k < KEIG; k++) acc[k] += evs[r][k] * hval;
        }
    }
    const float tau = taus[cc >> 2];
#pragma unroll
    for (int k = 0; k < KEIG; k++) {
        float f = expf(-eigval[g * KEIG + k] * tau);
        float* dst = &hs[(size_t)(g * KEIG + k) * CH + cc];
        float val = acc[k] * f;
        asm volatile("red.global.add.f32 [%0], %1;" :: "l"(dst), "f"(val) : "memory");
    }
}

// spec_bwd with fused lin bias: out = ev @ hs2 + bias
__global__ void spec_bwd(const float* __restrict__ ev, const float* __restrict__ hs2,
                         const float* __restrict__ bias, float* __restrict__ out) {
    const int g = blockIdx.x;
    const int nbase = g * NPG + blockIdx.y * 64;
    __shared__ float hss[KEIG][CH];
    __shared__ float evs[64][KEIG];
    for (int i = 0; i < KEIG; i++)
        hss[i][threadIdx.x] = hs2[(size_t)(g * KEIG + i) * CH + threadIdx.x];
    for (int i = threadIdx.x; i < 64 * KEIG; i += 256) {
        int r = i >> 5, kk = i & 31;
        evs[r][kk] = ev[(size_t)(nbase + r) * KEIG + kk];
    }
    __syncthreads();
    float b = bias[threadIdx.x];
    for (int r = 0; r < 64; r++) {
        float s = b;
#pragma unroll
        for (int k = 0; k < KEIG; k++) s += evs[r][k] * hss[k][threadIdx.x];
        out[(size_t)(nbase + r) * CH + threadIdx.x] = s;
    }
}

__global__ void final_kernel(const float* __restrict__ rep,
                             const float* __restrict__ hl,
                             float* __restrict__ out) {
    int t = blockIdx.x * blockDim.x + threadIdx.x;
    if (t >= NN * NB) return;
    int n = t >> 6;
    int b = t & 63;
    const float* p = rep + (size_t)n * NBP + b * 6;
    float Q[4][4];
    build_Q(p[0], p[1], p[2], p[3], p[4], p[5], Q);
    float4 hvv = *(const float4*)&hl[(size_t)n * CH + b * 4];
    float hr[4] = {hvv.x, hvv.y, hvv.z, hvv.w};
    float4 ov; float* o = &ov.x;
#pragma unroll
    for (int cc = 0; cc < 4; cc++)
        o[cc] = Q[0][cc] * hr[0] + Q[1][cc] * hr[1] + Q[2][cc] * hr[2] + Q[3][cc] * hr[3];
    *(float4*)&out[(size_t)n * CH + b * 4] = ov;
}

// ---------------- orchestration (forked-stream capture) ----------------
extern "C" void kernel_launch(void* const* d_in, const int* in_sizes, int n_in,
                              void* d_out, int out_size) {
    const float* x      = (const float*)d_in[0];
    const float* eigvec = (const float*)d_in[1];
    const float* eigval = (const float*)d_in[2];
    const float* taus   = (const float*)d_in[3];
    const float* enc_w  = (const float*)d_in[4];
    const float* enc_b  = (const float*)d_in[5];
    const float* self_w = (const float*)d_in[6];
    const float* self_b = (const float*)d_in[7];
    const float* nb_w   = (const float*)d_in[8];
    const float* nb_b   = (const float*)d_in[9];
    const float* dec_w  = (const float*)d_in[10];
    const float* dec_b  = (const float*)d_in[11];
    const float* lin_w  = (const float*)d_in[12];
    const float* lin_b  = (const float*)d_in[13];
    const int*   ei     = (const int*)d_in[14];
    float* out = (float*)d_out;

    const int E = in_sizes[14] / 2;

    float *h, *tmp, *agg, *rep, *hs, *hs2;
    __nv_bfloat16 *whi, *wlo;
    int *rowptr, *cursor, *csr;
    cudaGetSymbolAddress((void**)&h,      g_h);
    cudaGetSymbolAddress((void**)&tmp,    g_tmp);
    cudaGetSymbolAddress((void**)&agg,    g_agg);
    cudaGetSymbolAddress((void**)&rep,    g_rep);
    cudaGetSymbolAddress((void**)&hs,     g_hs);
    cudaGetSymbolAddress((void**)&hs2,    g_hs2);
    cudaGetSymbolAddress((void**)&whi,    g_whi);
    cudaGetSymbolAddress((void**)&wlo,    g_wlo);
    cudaGetSymbolAddress((void**)&rowptr, g_rowptr);
    cudaGetSymbolAddress((void**)&cursor, g_cursor);
    cudaGetSymbolAddress((void**)&csr,    g_csr);

    cudaFuncSetAttribute(tgemm<0>, cudaFuncAttributeMaxDynamicSharedMemorySize, SM_TOT);
    cudaFuncSetAttribute(tgemm<1>, cudaFuncAttributeMaxDynamicSharedMemorySize, SM_TOT);
    cudaFuncSetAttribute(tgemm<2>, cudaFuncAttributeMaxDynamicSharedMemorySize, SM_TOT);
    cudaFuncSetAttribute(tgemm<3>, cudaFuncAttributeMaxDynamicSharedMemorySize, SM_TOT);

    // side stream + events: created per call, intentionally not destroyed
    cudaStream_t s2;
    cudaStreamCreateWithFlags(&s2, cudaStreamNonBlocking);
    cudaEvent_t evRoot, evH, evG0, evT, evG1;
    cudaEventCreateWithFlags(&evRoot, cudaEventDisableTiming);
    cudaEventCreateWithFlags(&evH,    cudaEventDisableTiming);
    cudaEventCreateWithFlags(&evG0,   cudaEventDisableTiming);
    cudaEventCreateWithFlags(&evT,    cudaEventDisableTiming);
    cudaEventCreateWithFlags(&evG1,   cudaEventDisableTiming);

    dim3 gemm_grid(CH / 64, NN / 128);        // (4, 512)
    dim3 dec_grid(NBP / 64, NN / 128);        // (6, 512)
    dim3 hs_grid(CH / 64, (GG * KEIG) / 128); // (4, 16)

    // main: weight convert, zero hs; fork side stream for CSR build
    convert_all<<<(WTOT + 255) / 256, 256>>>(enc_w, self_w, nb_w, dec_w, lin_w, whi, wlo);
    cudaMemsetAsync(hs, 0, (size_t)GG * KEIG * CH * sizeof(float));
    cudaEventRecord(evRoot, 0);
    cudaStreamWaitEvent(s2, evRoot, 0);
    cudaMemsetAsync(rowptr, 0, (NN + 1) * sizeof(int), s2);
    csr_hist<<<(E + 255) / 256, 256, 0, s2>>>(ei, rowptr, E);
    csr_scan<<<1, 1024, 0, s2>>>(rowptr, cursor);
    csr_fill<<<(E + 255) / 256, 256, 0, s2>>>(ei, cursor, csr, E);

    // main: h = gelu(x @ enc_w + enc_b)
    tgemm<1><<<gemm_grid, 256, SM_TOT>>>(x, whi + OFF_ENC, wlo + OFF_ENC, enc_b,
                                         nullptr, nullptr, h, CH);
    cudaEventRecord(evH, 0);

    // ---- layer 0: gather(h) on s2 || self-GEMM(h) on main ----
    cudaStreamWaitEvent(s2, evH, 0);
    agg_gather<<<NN / 4, 256, 0, s2>>>(h, rowptr, csr, agg);
    cudaEventRecord(evG0, s2);

    tgemm<0><<<gemm_grid, 256, SM_TOT>>>(h, whi + OFF_SELF0, wlo + OFF_SELF0, self_b,
                                         nullptr, nullptr, rep, CH);
    cudaStreamWaitEvent(0, evG0, 0);
    tgemm<3><<<gemm_grid, 256, SM_TOT>>>(agg, whi + OFF_NB0, wlo + OFF_NB0, nb_b,
                                         rep, h, tmp, CH);
    cudaEventRecord(evT, 0);

    // ---- layer 1: gather(tmp) on s2 || self-GEMM(tmp) on main ----
    cudaStreamWaitEvent(s2, evT, 0);
    agg_gather<<<NN / 4, 256, 0, s2>>>(tmp, rowptr, csr, agg);
    cudaEventRecord(evG1, s2);

    tgemm<0><<<gemm_grid, 256, SM_TOT>>>(tmp, whi + OFF_SELF1, wlo + OFF_SELF1, self_b + CH,
                                         nullptr, nullptr, rep, CH);
    cudaStreamWaitEvent(0, evG1, 0);
    tgemm<3><<<gemm_grid, 256, SM_TOT>>>(agg, whi + OFF_NB1, wlo + OFF_NB1, nb_b + CH,
                                         rep, tmp, h, CH);

    // node_rep = h @ dec_w + dec_b
    tgemm<0><<<dec_grid, 256, SM_TOT>>>(h, whi + OFF_DEC, wlo + OFF_DEC, dec_b,
                                        nullptr, nullptr, rep, NBP);

    // Householder Q + forward rotate (hv into tmp)
    hh_kernel<<<NN * NB / 256, 256>>>(rep, x, tmp);

    // spectral filter: scaled partial reductions into hs, tiny GEMM, bwd, final
    spec_fwd<<<dim3(GG, 2, 8), 128>>>(eigvec, tmp, eigval, taus, hs);
    tgemm<2><<<hs_grid, 256, SM_TOT>>>(hs, whi + OFF_LIN, wlo + OFF_LIN, nullptr,
                                       nullptr, nullptr, hs2, CH);
    spec_bwd<<<dim3(GG, NPG / 64), 256>>>(eigvec, hs2, lin_b, tmp);

    // out = Q^T @ hl
    final_kernel<<<NN * NB / 256, 256>>>(rep, tmp, out);
}